// round 1
// baseline (speedup 1.0000x reference)
#include <cuda_runtime.h>
#include <cuda_bf16.h>
#include <cstdint>
#include <cstdio>

// Problem constants
constexpr int cB = 4;
constexpr int cS = 2048;
constexpr int cD = 2048;
constexpr int cH = 16;
constexpr int cHD = 128;
constexpr int cM = cB * cS;          // 8192 rows for the projection GEMMs

// Scratch: q, k, v, ctx  (each B*S*H*HD = 16M floats = 64 MB)
__device__ float g_q[(size_t)cB * cS * cH * cHD];
__device__ float g_k[(size_t)cB * cS * cH * cHD];
__device__ float g_v[(size_t)cB * cS * cH * cHD];
__device__ float g_ctx[(size_t)cB * cS * cH * cHD];

// ---------------------------------------------------------------------------
// SGEMM: C[M,N] = A[M,K] * B[K,N], all row-major, M%128==0, N%128==0, K%16==0
// 128x128 tile, BK=16, 256 threads, 8x8 microtile, float4 everywhere.
// ---------------------------------------------------------------------------
__global__ __launch_bounds__(256) void sgemm128(const float* __restrict__ A,
                                                const float* __restrict__ B,
                                                float* __restrict__ C,
                                                int M, int N, int K) {
    __shared__ float As[16][132];   // transposed A tile: As[k][row]
    __shared__ float Bs[16][128];   // Bs[k][col]

    const int t  = threadIdx.x;
    const int tx = t & 15;          // 0..15 -> column group
    const int ty = t >> 4;          // 0..15 -> row group

    const float* Ab = A + (size_t)blockIdx.y * 128 * K;
    const float* Bb = B + (size_t)blockIdx.x * 128;

    float acc[8][8];
#pragma unroll
    for (int i = 0; i < 8; i++)
#pragma unroll
        for (int j = 0; j < 8; j++) acc[i][j] = 0.f;

    for (int k0 = 0; k0 < K; k0 += 16) {
        // Load A tile (128 rows x 16 k), store transposed into As
#pragma unroll
        for (int i = 0; i < 2; i++) {
            int f   = t + i * 256;          // 0..511 float4 slots
            int row = f >> 2;               // 0..127
            int kq  = (f & 3) << 2;         // 0,4,8,12
            float4 v = *(const float4*)(Ab + (size_t)row * K + k0 + kq);
            As[kq + 0][row] = v.x;
            As[kq + 1][row] = v.y;
            As[kq + 2][row] = v.z;
            As[kq + 3][row] = v.w;
        }
        // Load B tile (16 k x 128 cols)
#pragma unroll
        for (int i = 0; i < 2; i++) {
            int f  = t + i * 256;
            int kr = f >> 5;                // 0..15
            int n4 = (f & 31) << 2;         // 0..124
            *(float4*)(&Bs[kr][n4]) = *(const float4*)(Bb + (size_t)(k0 + kr) * N + n4);
        }
        __syncthreads();

#pragma unroll
        for (int kk = 0; kk < 16; kk++) {
            float4 a0 = *(float4*)(&As[kk][ty * 8]);
            float4 a1 = *(float4*)(&As[kk][ty * 8 + 4]);
            float4 b0 = *(float4*)(&Bs[kk][tx * 8]);
            float4 b1 = *(float4*)(&Bs[kk][tx * 8 + 4]);
            float ar[8] = {a0.x, a0.y, a0.z, a0.w, a1.x, a1.y, a1.z, a1.w};
            float br[8] = {b0.x, b0.y, b0.z, b0.w, b1.x, b1.y, b1.z, b1.w};
#pragma unroll
            for (int i = 0; i < 8; i++)
#pragma unroll
                for (int j = 0; j < 8; j++) acc[i][j] += ar[i] * br[j];
        }
        __syncthreads();
    }

    // Write C
#pragma unroll
    for (int i = 0; i < 8; i++) {
        size_t row = (size_t)blockIdx.y * 128 + ty * 8 + i;
        float* Cp = C + row * N + blockIdx.x * 128 + tx * 8;
        float4 v0 = make_float4(acc[i][0], acc[i][1], acc[i][2], acc[i][3]);
        float4 v1 = make_float4(acc[i][4], acc[i][5], acc[i][6], acc[i][7]);
        *(float4*)(Cp)     = v0;
        *(float4*)(Cp + 4) = v1;
    }
}

// ---------------------------------------------------------------------------
// RoPE in-place on q and k.  Layout [b,s,h,d], pairs (j, j+64) within head.
// One thread per pair per (b,s,h); applies to both q and k (shared cos/sin).
// ---------------------------------------------------------------------------
__global__ __launch_bounds__(256) void rope_kernel(float* __restrict__ q,
                                                   float* __restrict__ k) {
    int p = blockIdx.x * blockDim.x + threadIdx.x;   // ((b*S+s)*H+h)*64 + j
    int j = p & 63;
    int s = (p >> 10) & (cS - 1);                    // (p/ (64*16)) % S
    size_t base = ((size_t)(p >> 6)) << 7;           // (p/64)*128

    // inv_freq = 10000^(-j/64) = exp(-ln(10000)/64 * j)
    float inv = expf((float)j * -0.14391156831212770f);
    float ang = (float)s * inv;
    float sn, cs;
    sincosf(ang, &sn, &cs);

    float q0 = q[base + j], q1 = q[base + 64 + j];
    q[base + j]      = q0 * cs - q1 * sn;
    q[base + 64 + j] = q1 * cs + q0 * sn;
    float k0 = k[base + j], k1 = k[base + 64 + j];
    k[base + j]      = k0 * cs - k1 * sn;
    k[base + 64 + j] = k1 * cs + k0 * sn;
}

// ---------------------------------------------------------------------------
// Flash attention (non-causal), fp32.
// Grid: (S/64 q-blocks, B*H).  256 threads.
// Q tile 64x128 resident; loop over K/V tiles of 64 rows with online softmax.
// Register tiling: thread (tx,ty) owns S rows {ty+16i}, S cols {tx+16j},
// O cols {tx+16c} -- strided so smem reads are broadcast / low-conflict.
// ---------------------------------------------------------------------------
constexpr int QS_LD = 132;   // 64 x 132 floats
constexpr int VS_LD = 136;   // 64 x 136
constexpr int PS_LD = 68;    // 64 x 68
constexpr int ATTN_SMEM_FLOATS = 64 * QS_LD * 2 + 64 * VS_LD + 64 * PS_LD;
constexpr int ATTN_SMEM_BYTES  = ATTN_SMEM_FLOATS * 4;   // 119,808 B

__global__ __launch_bounds__(256) void attn_kernel(const float* __restrict__ q,
                                                   const float* __restrict__ k,
                                                   const float* __restrict__ v,
                                                   float* __restrict__ ctx) {
    extern __shared__ float sm[];
    float* Qs = sm;                       // [64][132]
    float* Ks = Qs + 64 * QS_LD;          // [64][132]
    float* Vs = Ks + 64 * QS_LD;          // [64][136]
    float* Ps = Vs + 64 * VS_LD;          // [64][68]

    const int t  = threadIdx.x;
    const int tx = t & 15;
    const int ty = t >> 4;
    const int qb = blockIdx.x;                 // q block (64 rows)
    const int b  = blockIdx.y >> 4;
    const int h  = blockIdx.y & 15;

    // Load Q tile
#pragma unroll
    for (int i = 0; i < 8; i++) {
        int f  = t + i * 256;
        int r  = f >> 5;
        int d4 = (f & 31) << 2;
        size_t g = (((size_t)b * cS + qb * 64 + r) * cH + h) * cHD + d4;
        *(float4*)(Qs + r * QS_LD + d4) = *(const float4*)(q + g);
    }

    float m_i[4], l_i[4], oacc[4][8];
#pragma unroll
    for (int i = 0; i < 4; i++) {
        m_i[i] = -1e30f;
        l_i[i] = 0.f;
#pragma unroll
        for (int c = 0; c < 8; c++) oacc[i][c] = 0.f;
    }
    const float scale = 0.08838834764831845f;   // 1/sqrt(128)

    for (int kt = 0; kt < cS / 64; kt++) {
        __syncthreads();   // prev-iter PV readers done before overwriting K/V/P
        // Load K, V tiles
#pragma unroll
        for (int i = 0; i < 8; i++) {
            int f  = t + i * 256;
            int r  = f >> 5;
            int d4 = (f & 31) << 2;
            size_t g = (((size_t)b * cS + kt * 64 + r) * cH + h) * cHD + d4;
            *(float4*)(Ks + r * QS_LD + d4) = *(const float4*)(k + g);
            *(float4*)(Vs + r * VS_LD + d4) = *(const float4*)(v + g);
        }
        __syncthreads();

        // S = Q * K^T  (64x64 tile, thread owns rows ty+16i, cols tx+16j)
        float sacc[4][4];
#pragma unroll
        for (int i = 0; i < 4; i++)
#pragma unroll
            for (int j = 0; j < 4; j++) sacc[i][j] = 0.f;

#pragma unroll 8
        for (int k4 = 0; k4 < 32; k4++) {
            float4 aq[4], ak[4];
#pragma unroll
            for (int i = 0; i < 4; i++)
                aq[i] = *(float4*)(Qs + (ty + 16 * i) * QS_LD + k4 * 4);
#pragma unroll
            for (int j = 0; j < 4; j++)
                ak[j] = *(float4*)(Ks + (tx + 16 * j) * QS_LD + k4 * 4);
#pragma unroll
            for (int i = 0; i < 4; i++)
#pragma unroll
                for (int j = 0; j < 4; j++)
                    sacc[i][j] += aq[i].x * ak[j].x + aq[i].y * ak[j].y +
                                  aq[i].z * ak[j].z + aq[i].w * ak[j].w;
        }

        // Online softmax update (row stats reduced over the 16 tx lanes)
#pragma unroll
        for (int i = 0; i < 4; i++) {
            float rm = -1e30f;
#pragma unroll
            for (int j = 0; j < 4; j++) {
                sacc[i][j] *= scale;
                rm = fmaxf(rm, sacc[i][j]);
            }
#pragma unroll
            for (int off = 8; off; off >>= 1)
                rm = fmaxf(rm, __shfl_xor_sync(0xffffffffu, rm, off));
            float mn  = fmaxf(m_i[i], rm);
            float fac = __expf(m_i[i] - mn);
            m_i[i] = mn;
            float rs = 0.f;
#pragma unroll
            for (int j = 0; j < 4; j++) {
                float p = __expf(sacc[i][j] - mn);
                sacc[i][j] = p;
                rs += p;
            }
#pragma unroll
            for (int off = 8; off; off >>= 1)
                rs += __shfl_xor_sync(0xffffffffu, rs, off);
            l_i[i] = l_i[i] * fac + rs;
#pragma unroll
            for (int c = 0; c < 8; c++) oacc[i][c] *= fac;
#pragma unroll
            for (int j = 0; j < 4; j++)
                Ps[(ty + 16 * i) * PS_LD + tx + 16 * j] = sacc[i][j];
        }
        __syncthreads();

        // O += P * V   (thread owns O rows ty+16i, cols tx+16c)
#pragma unroll 4
        for (int jj = 0; jj < 64; jj++) {
            float pv[4];
#pragma unroll
            for (int i = 0; i < 4; i++) pv[i] = Ps[(ty + 16 * i) * PS_LD + jj];
#pragma unroll
            for (int c = 0; c < 8; c++) {
                float bv = Vs[jj * VS_LD + tx + 16 * c];
#pragma unroll
                for (int i = 0; i < 4; i++) oacc[i][c] += pv[i] * bv;
            }
        }
    }

    // Normalize and write ctx[b, s, h, d]
#pragma unroll
    for (int i = 0; i < 4; i++) {
        float inv = 1.0f / l_i[i];
        size_t base = (((size_t)b * cS + qb * 64 + ty + 16 * i) * cH + h) * cHD;
#pragma unroll
        for (int c = 0; c < 8; c++)
            ctx[base + tx + 16 * c] = oacc[i][c] * inv;
    }
}

// ---------------------------------------------------------------------------
// Launch
// ---------------------------------------------------------------------------
extern "C" void kernel_launch(void* const* d_in, const int* in_sizes, int n_in,
                              void* d_out, int out_size) {
    const float* x  = (const float*)d_in[0];
    const float* wq = (const float*)d_in[1];
    const float* wk = (const float*)d_in[2];
    const float* wv = (const float*)d_in[3];
    const float* wo = (const float*)d_in[4];
    float* out = (float*)d_out;

    float *qp, *kp, *vp, *cp;
    cudaGetSymbolAddress((void**)&qp, g_q);
    cudaGetSymbolAddress((void**)&kp, g_k);
    cudaGetSymbolAddress((void**)&vp, g_v);
    cudaGetSymbolAddress((void**)&cp, g_ctx);

    cudaFuncSetAttribute(attn_kernel, cudaFuncAttributeMaxDynamicSharedMemorySize,
                         ATTN_SMEM_BYTES);

    dim3 ggrid(cD / 128, cM / 128);   // (16, 64)

    // QKV projections
    sgemm128<<<ggrid, 256>>>(x, wq, qp, cM, cD, cD);
    sgemm128<<<ggrid, 256>>>(x, wk, kp, cM, cD, cD);
    sgemm128<<<ggrid, 256>>>(x, wv, vp, cM, cD, cD);

    // RoPE (q and k in one pass)
    int npairs = cB * cS * cH * 64;
    rope_kernel<<<npairs / 256, 256>>>(qp, kp);

    // Attention
    dim3 agrid(cS / 64, cB * cH);     // (32, 64)
    attn_kernel<<<agrid, 256, ATTN_SMEM_BYTES>>>(qp, kp, vp, cp);

    // Output projection
    sgemm128<<<ggrid, 256>>>(cp, wo, out, cM, cD, cD);
}

// round 4
// speedup vs baseline: 2.8263x; 2.8263x over previous
#include <cuda_runtime.h>
#include <cuda_bf16.h>
#include <cstdint>
#include <cstdio>

// Problem constants
constexpr int cB = 4;
constexpr int cS = 2048;
constexpr int cD = 2048;
constexpr int cH = 16;
constexpr int cHD = 128;
constexpr int cM = cB * cS;              // 8192

// Scratch (static device globals; allocation-free at runtime)
__device__ float g_q  [(size_t)cM * cD];     // 64 MB
__device__ float g_k  [(size_t)cM * cD];
__device__ float g_v  [(size_t)cM * cD];
__device__ float g_ctx[(size_t)cM * cD];
__device__ float g_xr [(size_t)cM * cD];     // tf32-rounded x
__device__ float g_wr [(size_t)4 * cD * cD]; // tf32-rounded wq,wk,wv,wo

// ---------------------------------------------------------------------------
// helpers
// ---------------------------------------------------------------------------
__device__ __forceinline__ uint32_t f2tf32(float f) {
    uint32_t u;
    asm("cvt.rna.tf32.f32 %0, %1;" : "=r"(u) : "f"(f));
    return u;
}
__device__ __forceinline__ uint32_t smaddr(const void* p) {
    return (uint32_t)__cvta_generic_to_shared(p);
}
__device__ __forceinline__ void cp_async16(uint32_t dst, const void* src) {
    asm volatile("cp.async.cg.shared.global [%0], [%1], 16;\n"
                 :: "r"(dst), "l"(src) : "memory");
}
__device__ __forceinline__ void cp_commit() {
    asm volatile("cp.async.commit_group;\n" ::: "memory");
}
__device__ __forceinline__ void mma_tf32(float* d, const uint32_t* a, const uint32_t* b) {
    asm volatile(
        "mma.sync.aligned.m16n8k8.row.col.f32.tf32.tf32.f32 "
        "{%0,%1,%2,%3}, {%4,%5,%6,%7}, {%8,%9}, {%0,%1,%2,%3};\n"
        : "+f"(d[0]), "+f"(d[1]), "+f"(d[2]), "+f"(d[3])
        : "r"(a[0]), "r"(a[1]), "r"(a[2]), "r"(a[3]), "r"(b[0]), "r"(b[1]));
}

// ---------------------------------------------------------------------------
// Elementwise tf32 rounding: out[i] = rna_tf32(in[i]), float4-vectorized
// ---------------------------------------------------------------------------
__global__ __launch_bounds__(256) void round_tf32(const float* __restrict__ in,
                                                  float* __restrict__ out, int n4) {
    int i = blockIdx.x * blockDim.x + threadIdx.x;
    if (i >= n4) return;
    float4 v = ((const float4*)in)[i];
    float4 o;
    o.x = __uint_as_float(f2tf32(v.x));
    o.y = __uint_as_float(f2tf32(v.y));
    o.z = __uint_as_float(f2tf32(v.z));
    o.w = __uint_as_float(f2tf32(v.w));
    ((float4*)out)[i] = o;
}

// ---------------------------------------------------------------------------
// TF32 tensor-core GEMM: C[M,N] = A[M,K]*B[K,N], row-major.
// A,B must be pre-rounded to tf32 values. 128x128x32 tile, 8 warps (2x4),
// warp tile 64x32, m16n8k8 mma, 3-stage cp.async pipeline.
// ---------------------------------------------------------------------------
constexpr int GA_LD = 36;    // A smem leading dim (floats)
constexpr int GB_LD = 132;   // B smem leading dim
constexpr int G_ASZ = 128 * GA_LD;          // 4608 floats
constexpr int G_BSZ = 32 * GB_LD;           // 4224 floats
constexpr int G_STAGE = G_ASZ + G_BSZ;      // 8832 floats
constexpr int G_NSTAGE = 3;
constexpr int GEMM_SMEM_BYTES = G_NSTAGE * G_STAGE * 4;   // 105,984 B

__global__ __launch_bounds__(256) void gemm_tf32(const float* __restrict__ A,
                                                 const float* __restrict__ B,
                                                 float* __restrict__ C,
                                                 int M, int N, int K) {
    extern __shared__ float sm[];
    const int t    = threadIdx.x;
    const int w    = t >> 5;
    const int lane = t & 31;
    const int g    = lane >> 2;
    const int tig  = lane & 3;
    const int wy   = w >> 2;         // 0..1
    const int wx   = w & 3;          // 0..3

    const float* Ab = A + (size_t)blockIdx.y * 128 * K;
    const float* Bb = B + (size_t)blockIdx.x * 128;

    float acc[4][4][4];
#pragma unroll
    for (int mt = 0; mt < 4; mt++)
#pragma unroll
        for (int nt = 0; nt < 4; nt++)
#pragma unroll
            for (int r = 0; r < 4; r++) acc[mt][nt][r] = 0.f;

    auto ld_stage = [&](int k0, int s) {
        float* As = sm + s * G_STAGE;
        float* Bs = As + G_ASZ;
#pragma unroll
        for (int i = 0; i < 4; i++) {       // A: 128 rows x 8 float4
            int f = t + i * 256;
            int r = f >> 3, cg = f & 7;
            cp_async16(smaddr(As + r * GA_LD + cg * 4),
                       Ab + (size_t)r * K + k0 + cg * 4);
        }
#pragma unroll
        for (int i = 0; i < 4; i++) {       // B: 32 rows x 32 float4
            int f = t + i * 256;
            int r = f >> 5, cg = f & 31;
            cp_async16(smaddr(Bs + r * GB_LD + cg * 4),
                       Bb + (size_t)(k0 + r) * N + cg * 4);
        }
    };

    const int niter = K / 32;                 // 64
    ld_stage(0, 0);
    cp_commit();
    ld_stage(32, 1);
    cp_commit();

    for (int it = 0; it < niter; ++it) {
        if (it + 1 < niter) {
            asm volatile("cp.async.wait_group 1;\n" ::: "memory");
        } else {
            asm volatile("cp.async.wait_group 0;\n" ::: "memory");
        }
        __syncthreads();

        // prefetch stage it+2 (its buffer was consumed in iteration it-1)
        if (it + 2 < niter) {
            ld_stage((it + 2) * 32, (it + 2) % G_NSTAGE);
            cp_commit();
        }

        const uint32_t* Au = (const uint32_t*)(sm + (it % G_NSTAGE) * G_STAGE);
        const uint32_t* Bu = Au + G_ASZ;
#pragma unroll
        for (int ks = 0; ks < 4; ks++) {
            const int kc = ks * 8;
            uint32_t a[4][4], b[4][2];
#pragma unroll
            for (int mt = 0; mt < 4; mt++) {
                int r = wy * 64 + mt * 16 + g;
                a[mt][0] = Au[(r)     * GA_LD + kc + tig];
                a[mt][1] = Au[(r + 8) * GA_LD + kc + tig];
                a[mt][2] = Au[(r)     * GA_LD + kc + tig + 4];
                a[mt][3] = Au[(r + 8) * GA_LD + kc + tig + 4];
            }
#pragma unroll
            for (int nt = 0; nt < 4; nt++) {
                int c = wx * 32 + nt * 8 + g;
                b[nt][0] = Bu[(kc + tig)     * GB_LD + c];
                b[nt][1] = Bu[(kc + tig + 4) * GB_LD + c];
            }
#pragma unroll
            for (int mt = 0; mt < 4; mt++)
#pragma unroll
                for (int nt = 0; nt < 4; nt++)
                    mma_tf32(acc[mt][nt], a[mt], b[nt]);
        }
        __syncthreads();
    }

    // Epilogue
#pragma unroll
    for (int mt = 0; mt < 4; mt++) {
#pragma unroll
        for (int nt = 0; nt < 4; nt++) {
            size_t r = (size_t)blockIdx.y * 128 + wy * 64 + mt * 16 + g;
            size_t c = (size_t)blockIdx.x * 128 + wx * 32 + nt * 8 + tig * 2;
            float2 v0 = make_float2(acc[mt][nt][0], acc[mt][nt][1]);
            float2 v1 = make_float2(acc[mt][nt][2], acc[mt][nt][3]);
            *(float2*)(C + r * N + c)       = v0;
            *(float2*)(C + (r + 8) * N + c) = v1;
        }
    }
}

// ---------------------------------------------------------------------------
// RoPE in-place on q and k (fp32).
// ---------------------------------------------------------------------------
__global__ __launch_bounds__(256) void rope_kernel(float* __restrict__ q,
                                                   float* __restrict__ k) {
    int p = blockIdx.x * blockDim.x + threadIdx.x;
    int j = p & 63;
    int s = (p >> 10) & (cS - 1);
    size_t base = ((size_t)(p >> 6)) << 7;

    float inv = expf((float)j * -0.14391156831212770f);
    float ang = (float)s * inv;
    float sn, cs;
    sincosf(ang, &sn, &cs);

    float q0 = q[base + j], q1 = q[base + 64 + j];
    q[base + j]      = q0 * cs - q1 * sn;
    q[base + 64 + j] = q1 * cs + q0 * sn;
    float k0 = k[base + j], k1 = k[base + 64 + j];
    k[base + j]      = k0 * cs - k1 * sn;
    k[base + 64 + j] = k1 * cs + k0 * sn;
}

// ---------------------------------------------------------------------------
// Flash attention with tf32 mma for QK^T and PV.
// 128 q-rows per CTA, 8 warps, warp w owns rows w*16..w*16+15.
// K/V tiles of 64 rows. ctx output is tf32-rounded (feeds out-proj GEMM).
// ---------------------------------------------------------------------------
constexpr int AQ_LD = 132;
constexpr int AK_LD = 132;
constexpr int AV_LD = 132;
constexpr int AP_LD = 68;
constexpr int A_QSZ = 128 * AQ_LD;
constexpr int A_KSZ = 64 * AK_LD;
constexpr int A_VSZ = 64 * AV_LD;
constexpr int A_PSZ = 128 * AP_LD;
constexpr int ATTN_SMEM_BYTES = (A_QSZ + A_KSZ + A_VSZ + A_PSZ) * 4;  // 169,984

__global__ __launch_bounds__(256) void attn_mma(const float* __restrict__ q,
                                                const float* __restrict__ k,
                                                const float* __restrict__ v,
                                                float* __restrict__ ctx) {
    extern __shared__ float sm[];
    float* Qs = sm;
    float* Ks = Qs + A_QSZ;
    float* Vs = Ks + A_KSZ;
    float* Ps = Vs + A_VSZ;
    uint32_t* Qu = (uint32_t*)Qs;
    uint32_t* Ku = (uint32_t*)Ks;
    uint32_t* Vu = (uint32_t*)Vs;
    uint32_t* Pu = (uint32_t*)Ps;

    const int t    = threadIdx.x;
    const int w    = t >> 5;
    const int lane = t & 31;
    const int g    = lane >> 2;
    const int tig  = lane & 3;
    const int m0   = w * 16;
    const int qb   = blockIdx.x;
    const int b    = blockIdx.y >> 4;
    const int h    = blockIdx.y & 15;
    const float scale = 0.08838834764831845f;   // 1/sqrt(128)

    // Load Q (scaled, tf32-rounded)
#pragma unroll
    for (int i = 0; i < 16; i++) {
        int f = t + i * 256;
        int r = f >> 5, cg = f & 31;
        size_t gidx = (((size_t)b * cS + qb * 128 + r) * cH + h) * cHD + cg * 4;
        float4 vq = *(const float4*)(q + gidx);
        uint32_t* d = Qu + r * AQ_LD + cg * 4;
        d[0] = f2tf32(vq.x * scale);
        d[1] = f2tf32(vq.y * scale);
        d[2] = f2tf32(vq.z * scale);
        d[3] = f2tf32(vq.w * scale);
    }

    float oacc[16][4];
#pragma unroll
    for (int nt = 0; nt < 16; nt++)
#pragma unroll
        for (int r = 0; r < 4; r++) oacc[nt][r] = 0.f;
    float mrow[2] = {-1e30f, -1e30f};
    float lrow[2] = {0.f, 0.f};

    for (int kt = 0; kt < cS / 64; kt++) {
        __syncthreads();   // protect K/V from previous iteration's readers
#pragma unroll
        for (int i = 0; i < 8; i++) {
            int f = t + i * 256;
            int r = f >> 5, cg = f & 31;
            size_t gidx = (((size_t)b * cS + kt * 64 + r) * cH + h) * cHD + cg * 4;
            float4 vk = *(const float4*)(k + gidx);
            float4 vv = *(const float4*)(v + gidx);
            uint32_t* dk = Ku + r * AK_LD + cg * 4;
            dk[0] = f2tf32(vk.x); dk[1] = f2tf32(vk.y);
            dk[2] = f2tf32(vk.z); dk[3] = f2tf32(vk.w);
            uint32_t* dv = Vu + r * AV_LD + cg * 4;
            dv[0] = f2tf32(vv.x); dv[1] = f2tf32(vv.y);
            dv[2] = f2tf32(vv.z); dv[3] = f2tf32(vv.w);
        }
        __syncthreads();

        // ---- S = Q * K^T  (16 x 64 per warp) ----
        float sacc[8][4];
#pragma unroll
        for (int nt = 0; nt < 8; nt++)
#pragma unroll
            for (int r = 0; r < 4; r++) sacc[nt][r] = 0.f;

#pragma unroll
        for (int ks = 0; ks < 16; ks++) {
            const int kc = ks * 8;
            uint32_t a[4];
            a[0] = Qu[(m0 + g)     * AQ_LD + kc + tig];
            a[1] = Qu[(m0 + g + 8) * AQ_LD + kc + tig];
            a[2] = Qu[(m0 + g)     * AQ_LD + kc + tig + 4];
            a[3] = Qu[(m0 + g + 8) * AQ_LD + kc + tig + 4];
#pragma unroll
            for (int nt = 0; nt < 8; nt++) {
                uint32_t bfr[2];
                bfr[0] = Ku[(nt * 8 + g) * AK_LD + kc + tig];
                bfr[1] = Ku[(nt * 8 + g) * AK_LD + kc + tig + 4];
                mma_tf32(sacc[nt], a, bfr);
            }
        }

        // ---- online softmax (rows g and g+8 within warp band) ----
#pragma unroll
        for (int r2 = 0; r2 < 2; r2++) {
            float mx = -1e30f;
#pragma unroll
            for (int nt = 0; nt < 8; nt++) {
                mx = fmaxf(mx, sacc[nt][2 * r2]);
                mx = fmaxf(mx, sacc[nt][2 * r2 + 1]);
            }
            mx = fmaxf(mx, __shfl_xor_sync(0xffffffffu, mx, 1));
            mx = fmaxf(mx, __shfl_xor_sync(0xffffffffu, mx, 2));
            float mn  = fmaxf(mrow[r2], mx);
            float fac = __expf(mrow[r2] - mn);
            mrow[r2] = mn;
            float rs = 0.f;
            int prow = (m0 + g + 8 * r2) * AP_LD;
#pragma unroll
            for (int nt = 0; nt < 8; nt++) {
                float p0 = __expf(sacc[nt][2 * r2]     - mn);
                float p1 = __expf(sacc[nt][2 * r2 + 1] - mn);
                rs += p0 + p1;
                Pu[prow + nt * 8 + 2 * tig]     = f2tf32(p0);
                Pu[prow + nt * 8 + 2 * tig + 1] = f2tf32(p1);
            }
            rs += __shfl_xor_sync(0xffffffffu, rs, 1);
            rs += __shfl_xor_sync(0xffffffffu, rs, 2);
            lrow[r2] = lrow[r2] * fac + rs;
#pragma unroll
            for (int nt = 0; nt < 16; nt++) {
                oacc[nt][2 * r2]     *= fac;
                oacc[nt][2 * r2 + 1] *= fac;
            }
        }
        __syncwarp();

        // ---- O += P * V  (16 x 128 per warp, k = 64) ----
#pragma unroll
        for (int ks = 0; ks < 8; ks++) {
            const int kc = ks * 8;
            uint32_t a[4];
            a[0] = Pu[(m0 + g)     * AP_LD + kc + tig];
            a[1] = Pu[(m0 + g + 8) * AP_LD + kc + tig];
            a[2] = Pu[(m0 + g)     * AP_LD + kc + tig + 4];
            a[3] = Pu[(m0 + g + 8) * AP_LD + kc + tig + 4];
#pragma unroll
            for (int nt = 0; nt < 16; nt++) {
                uint32_t bfr[2];
                bfr[0] = Vu[(kc + tig)     * AV_LD + nt * 8 + g];
                bfr[1] = Vu[(kc + tig + 4) * AV_LD + nt * 8 + g];
                mma_tf32(oacc[nt], a, bfr);
            }
        }
    }

    // Epilogue: normalize, tf32-round (feeds the tf32 out-proj), store
#pragma unroll
    for (int r2 = 0; r2 < 2; r2++) {
        float inv = 1.0f / lrow[r2];
        size_t base = (((size_t)b * cS + qb * 128 + m0 + g + 8 * r2) * cH + h) * cHD;
#pragma unroll
        for (int nt = 0; nt < 16; nt++) {
            float o0 = oacc[nt][2 * r2]     * inv;
            float o1 = oacc[nt][2 * r2 + 1] * inv;
            float2 val = make_float2(__uint_as_float(f2tf32(o0)),
                                     __uint_as_float(f2tf32(o1)));
            *(float2*)(ctx + base + nt * 8 + 2 * tig) = val;
        }
    }
}

// ---------------------------------------------------------------------------
// Launch
// ---------------------------------------------------------------------------
extern "C" void kernel_launch(void* const* d_in, const int* in_sizes, int n_in,
                              void* d_out, int out_size) {
    const float* x  = (const float*)d_in[0];
    const float* wq = (const float*)d_in[1];
    const float* wk = (const float*)d_in[2];
    const float* wv = (const float*)d_in[3];
    const float* wo = (const float*)d_in[4];
    float* out = (float*)d_out;

    float *qp, *kp, *vp, *cp, *xr, *wr;
    cudaGetSymbolAddress((void**)&qp, g_q);
    cudaGetSymbolAddress((void**)&kp, g_k);
    cudaGetSymbolAddress((void**)&vp, g_v);
    cudaGetSymbolAddress((void**)&cp, g_ctx);
    cudaGetSymbolAddress((void**)&xr, g_xr);
    cudaGetSymbolAddress((void**)&wr, g_wr);

    cudaFuncSetAttribute(gemm_tf32, cudaFuncAttributeMaxDynamicSharedMemorySize,
                         GEMM_SMEM_BYTES);
    cudaFuncSetAttribute(attn_mma, cudaFuncAttributeMaxDynamicSharedMemorySize,
                         ATTN_SMEM_BYTES);

    const size_t WSZ = (size_t)cD * cD;      // 4M floats per weight

    // tf32 pre-rounding (x + 4 weights)
    {
        int n4 = (int)((size_t)cM * cD / 4);
        round_tf32<<<(n4 + 255) / 256, 256>>>(x, xr, n4);
        int w4 = (int)(WSZ / 4);
        round_tf32<<<(w4 + 255) / 256, 256>>>(wq, wr + 0 * WSZ, w4);
        round_tf32<<<(w4 + 255) / 256, 256>>>(wk, wr + 1 * WSZ, w4);
        round_tf32<<<(w4 + 255) / 256, 256>>>(wv, wr + 2 * WSZ, w4);
        round_tf32<<<(w4 + 255) / 256, 256>>>(wo, wr + 3 * WSZ, w4);
    }

    dim3 ggrid(cD / 128, cM / 128);   // (16, 64)

    // QKV projections (tensor cores)
    gemm_tf32<<<ggrid, 256, GEMM_SMEM_BYTES>>>(xr, wr + 0 * WSZ, qp, cM, cD, cD);
    gemm_tf32<<<ggrid, 256, GEMM_SMEM_BYTES>>>(xr, wr + 1 * WSZ, kp, cM, cD, cD);
    gemm_tf32<<<ggrid, 256, GEMM_SMEM_BYTES>>>(xr, wr + 2 * WSZ, vp, cM, cD, cD);

    // RoPE
    int npairs = cB * cS * cH * 64;
    rope_kernel<<<npairs / 256, 256>>>(qp, kp);

    // Attention (tensor cores)
    dim3 agrid(cS / 128, cB * cH);    // (16, 64)
    attn_mma<<<agrid, 256, ATTN_SMEM_BYTES>>>(qp, kp, vp, cp);

    // Output projection (ctx already tf32-rounded by attn epilogue)
    gemm_tf32<<<ggrid, 256, GEMM_SMEM_BYTES>>>(cp, wr + 3 * WSZ, out, cM, cD, cD);
}